// round 9
// baseline (speedup 1.0000x reference)
#include <cuda_runtime.h>
#include <cuda_bf16.h>

// Problem shape (fixed by the reference)
#define NWALK 4096
#define NIN   24      // NPART*NDIM
#define HID   256
#define TPW   16      // threads cooperating on one walker
#define BLOCK 128

// c = 2*log2(e): folds exp(2a) into a single ex2.approx on the pre-scaled dot.
#define CFOLD 2.8853900817779268f

// Prepped weight storage:
//  gW1t: 6 planes of [HID] float4; plane p, entry j = c*W1[4p..4p+3][j]
//        lanes with 16 consecutive j read one contiguous 256B segment (coalesced).
//  gP[j] = (c*b1_j,  4*W2_j/c,  -8*S_j*W2_j,  0)   with S_j = sum_i W1[i][j]^2
__device__ float4 gW1t[6 * HID];
__device__ float4 gP[HID];

// ---- packed f32x2 helpers (sm_100a FFMA2 path; ptxas never auto-fuses) ----
__device__ __forceinline__ unsigned long long pk2(float lo, float hi) {
    unsigned long long r;
    asm("mov.b64 %0, {%1, %2};" : "=l"(r) : "f"(lo), "f"(hi));
    return r;
}
__device__ __forceinline__ void upk2(unsigned long long v, float& lo, float& hi) {
    asm("mov.b64 {%0, %1}, %2;" : "=f"(lo), "=f"(hi) : "l"(v));
}
__device__ __forceinline__ unsigned long long ffma2(unsigned long long a,
                                                    unsigned long long b,
                                                    unsigned long long c) {
    unsigned long long d;
    asm("fma.rn.f32x2 %0, %1, %2, %3;" : "=l"(d) : "l"(a), "l"(b), "l"(c));
    return d;
}
__device__ __forceinline__ unsigned long long fadd2(unsigned long long a,
                                                    unsigned long long b) {
    unsigned long long d;
    asm("add.rn.f32x2 %0, %1, %2;" : "=l"(d) : "l"(a), "l"(b));
    return d;
}

__global__ __launch_bounds__(128)
void prep_kernel(const float* __restrict__ W1,
                 const float* __restrict__ b1,
                 const float* __restrict__ W2)
{
    const int j = blockIdx.x * blockDim.x + threadIdx.x;
    if (j >= HID) return;
    float w[NIN];
    float s = 0.f;
    #pragma unroll
    for (int i = 0; i < NIN; i++) {            // coalesced over j
        w[i] = W1[i * HID + j];
        s = fmaf(w[i], w[i], s);
    }
    #pragma unroll
    for (int p = 0; p < 6; p++)
        gW1t[p * HID + j] = make_float4(CFOLD * w[4*p],   CFOLD * w[4*p+1],
                                        CFOLD * w[4*p+2], CFOLD * w[4*p+3]);
    const float w2 = W2[j];
    gP[j] = make_float4(CFOLD * b1[j], 4.f * w2 / CFOLD, -8.f * s * w2, 0.f);
}

__global__ __launch_bounds__(BLOCK)
void kin_kernel(const float* __restrict__ x,
                float* __restrict__ out)
{
    const int gt     = blockIdx.x * BLOCK + threadIdx.x;
    const int walker = gt >> 4;          // / TPW
    const int sub    = gt & (TPW - 1);

    // This walker's z, packed as 12 f32x2 (96B, 16B-aligned).
    const ulonglong2* zp = reinterpret_cast<const ulonglong2*>(x + walker * NIN);
    unsigned long long z_pk[12];
    #pragma unroll
    for (int c = 0; c < 6; c++) {
        ulonglong2 v = zp[c];
        z_pk[2*c] = v.x; z_pk[2*c + 1] = v.y;
    }

    unsigned long long g_pk[12];
    #pragma unroll
    for (int p = 0; p < 12; p++) g_pk[p] = 0ull;
    float lap = 0.f;

    const ulonglong2* wt = reinterpret_cast<const ulonglong2*>(gW1t);

    // Each lane handles columns j = jj*16 + sub (coalesced LDG.128)
    #pragma unroll 4
    for (int jj = 0; jj < HID / TPW; jj++) {
        const int j = (jj << 4) + sub;

        unsigned long long w_pk[12];
        #pragma unroll
        for (int c = 0; c < 6; c++) {
            ulonglong2 v = __ldg(&wt[c * HID + j]);
            w_pk[2*c] = v.x; w_pk[2*c + 1] = v.y;
        }
        const float4 p = __ldg(&gP[j]);        // (c*b1, 4*W2/c, -8*S*W2, 0)

        // a' = c*(b1 + z.W1[:,j])  via 4 packed accumulators (12 FFMA2)
        unsigned long long a0 = pk2(p.x, 0.f), a1 = 0ull, a2 = 0ull, a3 = 0ull;
        #pragma unroll
        for (int q = 0; q < 12; q += 4) {
            a0 = ffma2(z_pk[q],     w_pk[q],     a0);
            a1 = ffma2(z_pk[q + 1], w_pk[q + 1], a1);
            a2 = ffma2(z_pk[q + 2], w_pk[q + 2], a2);
            a3 = ffma2(z_pk[q + 3], w_pk[q + 3], a3);
        }
        float lo, hi;
        upk2(fadd2(fadd2(a0, a1), fadd2(a2, a3)), lo, hi);
        const float ap = lo + hi;              // = 2a*log2(e)

        // e^{2a} = 2^{ap};  r = 1/(e+1);  h = 1-2r;  (1-h^2)/4 = r - r^2
        float e;  asm("ex2.approx.f32 %0, %1;" : "=f"(e) : "f"(ap));
        float r;  { const float ep1 = e + 1.f;
                    asm("rcp.approx.f32 %0, %1;" : "=f"(r) : "f"(ep1)); }
        const float h  = fmaf(-2.f, r, 1.f);
        const float rr = fmaf(-r, r, r);       // (1-h^2)/4, cancellation-free
        const float u  = rr * p.y;             // = (1-h^2)*W2/c
        lap = fmaf(rr * h, p.z, lap);          // += (1-h^2)*h*(-2*S*W2)

        // gradient accumulation: g += (c*W1[:,j]) * u  (12 FFMA2)
        const unsigned long long ud = pk2(u, u);
        #pragma unroll
        for (int q = 0; q < 12; q++) g_pk[q] = ffma2(w_pk[q], ud, g_pk[q]);
    }

    // Butterfly reduction across the 16 lanes of this walker
    #pragma unroll
    for (int ofs = 1; ofs < TPW; ofs <<= 1) {
        #pragma unroll
        for (int q = 0; q < 12; q++)
            g_pk[q] = fadd2(g_pk[q], __shfl_xor_sync(0xffffffffu, g_pk[q], ofs));
        lap += __shfl_xor_sync(0xffffffffu, lap, ofs);
    }

    if (sub == 0) {
        unsigned long long gs = 0ull;
        #pragma unroll
        for (int q = 0; q < 12; q++) gs = ffma2(g_pk[q], g_pk[q], gs);
        float lo, hi;
        upk2(gs, lo, hi);
        out[walker] = -0.5f * (lap + (lo + hi));
    }
}

extern "C" void kernel_launch(void* const* d_in, const int* in_sizes, int n_in,
                              void* d_out, int out_size)
{
    // metadata order: x [4096*8*3], W1 [24*256], b1 [256], W2 [256], b2 [1]
    const float* x  = (const float*)d_in[0];
    const float* W1 = (const float*)d_in[1];
    const float* b1 = (const float*)d_in[2];
    const float* W2 = (const float*)d_in[3];
    float* out = (float*)d_out;

    prep_kernel<<<2, 128>>>(W1, b1, W2);
    kin_kernel<<<(NWALK * TPW) / BLOCK, BLOCK>>>(x, out);   // 512 blocks
}

// round 10
// speedup vs baseline: 1.0266x; 1.0266x over previous
#include <cuda_runtime.h>
#include <cuda_bf16.h>

// Problem shape (fixed by the reference)
#define NWALK 4096
#define NIN   24      // NPART*NDIM
#define HID   256
#define TPW   16      // lanes per walker-pair group
#define BLOCK 128

// Prepped weight storage:
//  gW1t: 6 planes of [HID] float4; plane p, entry j = W1[4p..4p+3][j] (raw).
//        16 consecutive j within a lane-group -> one contiguous 256B segment.
//  gP[j] = (b1_j, W2_j, -2*S_j*W2_j, 0)  with S_j = sum_i W1[i][j]^2
__device__ float4 gW1t[6 * HID];
__device__ float4 gP[HID];

// ---- packed f32x2 helpers (sm_100a FFMA2 path; ptxas never auto-fuses) ----
__device__ __forceinline__ unsigned long long pk2(float lo, float hi) {
    unsigned long long r;
    asm("mov.b64 %0, {%1, %2};" : "=l"(r) : "f"(lo), "f"(hi));
    return r;
}
__device__ __forceinline__ void upk2(unsigned long long v, float& lo, float& hi) {
    asm("mov.b64 {%0, %1}, %2;" : "=f"(lo), "=f"(hi) : "l"(v));
}
__device__ __forceinline__ unsigned long long ffma2(unsigned long long a,
                                                    unsigned long long b,
                                                    unsigned long long c) {
    unsigned long long d;
    asm("fma.rn.f32x2 %0, %1, %2, %3;" : "=l"(d) : "l"(a), "l"(b), "l"(c));
    return d;
}
__device__ __forceinline__ unsigned long long fadd2(unsigned long long a,
                                                    unsigned long long b) {
    unsigned long long d;
    asm("add.rn.f32x2 %0, %1, %2;" : "=l"(d) : "l"(a), "l"(b));
    return d;
}
__device__ __forceinline__ float tanh_hw(float a) {
    float h;
    asm("tanh.approx.f32 %0, %1;" : "=f"(h) : "f"(a));
    return h;
}

__global__ __launch_bounds__(128)
void prep_kernel(const float* __restrict__ W1,
                 const float* __restrict__ b1,
                 const float* __restrict__ W2)
{
    const int j = blockIdx.x * blockDim.x + threadIdx.x;
    if (j >= HID) return;
    float w[NIN];
    float s = 0.f;
    #pragma unroll
    for (int i = 0; i < NIN; i++) {            // coalesced over j
        w[i] = W1[i * HID + j];
        s = fmaf(w[i], w[i], s);
    }
    #pragma unroll
    for (int p = 0; p < 6; p++)
        gW1t[p * HID + j] = make_float4(w[4*p], w[4*p+1], w[4*p+2], w[4*p+3]);
    const float w2 = W2[j];
    gP[j] = make_float4(b1[j], w2, -2.f * s * w2, 0.f);
}

__global__ __launch_bounds__(BLOCK)
void kin_kernel(const float* __restrict__ x,
                float* __restrict__ out)
{
    const int gt    = blockIdx.x * BLOCK + threadIdx.x;
    const int group = gt >> 4;           // walker pair id
    const int sub   = gt & (TPW - 1);

    // Two walkers per group: A = 2*group, B = 2*group+1 (each 96B, 16B-aligned)
    const ulonglong2* zA4 = reinterpret_cast<const ulonglong2*>(x + (2 * group)     * NIN);
    const ulonglong2* zB4 = reinterpret_cast<const ulonglong2*>(x + (2 * group + 1) * NIN);
    unsigned long long zA[12], zB[12];
    #pragma unroll
    for (int c = 0; c < 6; c++) {
        ulonglong2 va = zA4[c]; zA[2*c] = va.x; zA[2*c+1] = va.y;
        ulonglong2 vb = zB4[c]; zB[2*c] = vb.x; zB[2*c+1] = vb.y;
    }

    unsigned long long gA[12], gB[12];
    #pragma unroll
    for (int q = 0; q < 12; q++) { gA[q] = 0ull; gB[q] = 0ull; }
    float lapA = 0.f, lapB = 0.f;

    const ulonglong2* wt = reinterpret_cast<const ulonglong2*>(gW1t);

    // Each lane handles columns j = jj*16 + sub; both warp halves fetch the
    // SAME weight addresses -> warp-level dedup; weights amortized over 2 walkers.
    #pragma unroll 2
    for (int jj = 0; jj < HID / TPW; jj++) {
        const int j = (jj << 4) + sub;

        unsigned long long w_pk[12];
        #pragma unroll
        for (int c = 0; c < 6; c++) {
            ulonglong2 v = __ldg(&wt[c * HID + j]);
            w_pk[2*c] = v.x; w_pk[2*c + 1] = v.y;
        }
        const float4 p = __ldg(&gP[j]);        // (b1, W2, -2*S*W2, 0)

        // dots for both walkers (packed over i): 12 FFMA2 each
        unsigned long long aA0 = pk2(p.x, 0.f), aA1 = 0ull, aA2 = 0ull, aA3 = 0ull;
        unsigned long long aB0 = pk2(p.x, 0.f), aB1 = 0ull, aB2 = 0ull, aB3 = 0ull;
        #pragma unroll
        for (int q = 0; q < 12; q += 4) {
            aA0 = ffma2(zA[q],     w_pk[q],     aA0);
            aA1 = ffma2(zA[q + 1], w_pk[q + 1], aA1);
            aA2 = ffma2(zA[q + 2], w_pk[q + 2], aA2);
            aA3 = ffma2(zA[q + 3], w_pk[q + 3], aA3);
            aB0 = ffma2(zB[q],     w_pk[q],     aB0);
            aB1 = ffma2(zB[q + 1], w_pk[q + 1], aB1);
            aB2 = ffma2(zB[q + 2], w_pk[q + 2], aB2);
            aB3 = ffma2(zB[q + 3], w_pk[q + 3], aB3);
        }
        float loA, hiA, loB, hiB;
        upk2(fadd2(fadd2(aA0, aA1), fadd2(aA2, aA3)), loA, hiA);
        upk2(fadd2(fadd2(aB0, aB1), fadd2(aB2, aB3)), loB, hiB);
        const float aAv = loA + hiA;
        const float aBv = loB + hiB;

        // hardware tanh; om = 1-h^2 (non-saturated regime -> benign error)
        const float hA  = tanh_hw(aAv);
        const float hB  = tanh_hw(aBv);
        const float omA = fmaf(-hA, hA, 1.f);
        const float omB = fmaf(-hB, hB, 1.f);
        const float uA  = omA * p.y;
        const float uB  = omB * p.y;
        lapA = fmaf(omA * hA, p.z, lapA);      // += (1-h^2)*h*(-2*S*W2)
        lapB = fmaf(omB * hB, p.z, lapB);

        // gradient accumulation, packed over i: 12 FFMA2 per walker
        const unsigned long long dA = pk2(uA, uA);
        const unsigned long long dB = pk2(uB, uB);
        #pragma unroll
        for (int q = 0; q < 12; q++) {
            gA[q] = ffma2(w_pk[q], dA, gA[q]);
            gB[q] = ffma2(w_pk[q], dB, gB[q]);
        }
    }

    // Butterfly reduction across the 16 lanes of this group
    #pragma unroll
    for (int ofs = 1; ofs < TPW; ofs <<= 1) {
        #pragma unroll
        for (int q = 0; q < 12; q++) {
            gA[q] = fadd2(gA[q], __shfl_xor_sync(0xffffffffu, gA[q], ofs));
            gB[q] = fadd2(gB[q], __shfl_xor_sync(0xffffffffu, gB[q], ofs));
        }
        lapA += __shfl_xor_sync(0xffffffffu, lapA, ofs);
        lapB += __shfl_xor_sync(0xffffffffu, lapB, ofs);
    }

    if (sub == 0) {
        unsigned long long gsA = 0ull, gsB = 0ull;
        #pragma unroll
        for (int q = 0; q < 12; q++) {
            gsA = ffma2(gA[q], gA[q], gsA);
            gsB = ffma2(gB[q], gB[q], gsB);
        }
        float la, ha, lb, hb;
        upk2(gsA, la, ha);
        upk2(gsB, lb, hb);
        float2 res;
        res.x = -0.5f * (lapA + (la + ha));
        res.y = -0.5f * (lapB + (lb + hb));
        *reinterpret_cast<float2*>(out + 2 * group) = res;   // 8B-aligned
    }
}

extern "C" void kernel_launch(void* const* d_in, const int* in_sizes, int n_in,
                              void* d_out, int out_size)
{
    // metadata order: x [4096*8*3], W1 [24*256], b1 [256], W2 [256], b2 [1]
    const float* x  = (const float*)d_in[0];
    const float* W1 = (const float*)d_in[1];
    const float* b1 = (const float*)d_in[2];
    const float* W2 = (const float*)d_in[3];
    float* out = (float*)d_out;

    prep_kernel<<<2, 128>>>(W1, b1, W2);
    // groups = NWALK/2 = 2048; threads = 32768; 256 blocks
    kin_kernel<<<(NWALK / 2) * TPW / BLOCK, BLOCK>>>(x, out);
}

// round 11
// speedup vs baseline: 1.3499x; 1.3149x over previous
#include <cuda_runtime.h>
#include <cuda_bf16.h>

// Problem shape (fixed by the reference)
#define NWALK 4096
#define NIN   24      // NPART*NDIM
#define HID   256
#define TPW   16      // lanes per walker-pair group
#define BLOCK 128
#define STR   28      // padded smem stride (words): conflict-free LDS.128 across 8-lane phases

// ---- packed f32x2 helpers (sm_100a FFMA2 path; ptxas never auto-fuses) ----
__device__ __forceinline__ unsigned long long pk2(float lo, float hi) {
    unsigned long long r;
    asm("mov.b64 %0, {%1, %2};" : "=l"(r) : "f"(lo), "f"(hi));
    return r;
}
__device__ __forceinline__ void upk2(unsigned long long v, float& lo, float& hi) {
    asm("mov.b64 {%0, %1}, %2;" : "=f"(lo), "=f"(hi) : "l"(v));
}
__device__ __forceinline__ unsigned long long ffma2(unsigned long long a,
                                                    unsigned long long b,
                                                    unsigned long long c) {
    unsigned long long d;
    asm("fma.rn.f32x2 %0, %1, %2, %3;" : "=l"(d) : "l"(a), "l"(b), "l"(c));
    return d;
}
__device__ __forceinline__ unsigned long long fadd2(unsigned long long a,
                                                    unsigned long long b) {
    unsigned long long d;
    asm("add.rn.f32x2 %0, %1, %2;" : "=l"(d) : "l"(a), "l"(b));
    return d;
}
__device__ __forceinline__ float tanh_hw(float a) {
    float h;
    asm("tanh.approx.f32 %0, %1;" : "=f"(h) : "f"(a));
    return h;
}

__global__ __launch_bounds__(BLOCK)
void kin_kernel(const float* __restrict__ x,
                const float* __restrict__ W1,
                const float* __restrict__ b1,
                const float* __restrict__ W2,
                float* __restrict__ out)
{
    __shared__ float  sW1t[HID * STR];   // [j][i], padded: 28KB
    __shared__ float4 sP[HID];           // (b1_j, W2_j, -2*S_j*W2_j, 0): 4KB

    const int tid = threadIdx.x;

    // ---- Preamble: coalesced high-MLP fill + transpose (one burst) ----
    #pragma unroll
    for (int t = 0; t < (NIN * HID) / BLOCK; t++) {     // 48 coalesced LDGs/thread
        const int k = t * BLOCK + tid;                  // k = i*HID + j
        const int i = k >> 8;
        const int j = k & (HID - 1);
        sW1t[j * STR + i] = W1[k];
    }
    {   // b1, W2 (2 loads each)
        const int j0 = tid, j1 = tid + BLOCK;
        const float b0 = b1[j0], b1v = b1[j1];
        const float w0 = W2[j0], w1v = W2[j1];
        __syncthreads();                                // sW1t ready
        float s0 = 0.f, s1 = 0.f;
        #pragma unroll
        for (int i = 0; i < NIN; i++) {
            const float a = sW1t[j0 * STR + i];
            const float b = sW1t[j1 * STR + i];
            s0 = fmaf(a, a, s0);
            s1 = fmaf(b, b, s1);
        }
        sP[j0] = make_float4(b0,  w0,  -2.f * s0 * w0,  0.f);
        sP[j1] = make_float4(b1v, w1v, -2.f * s1 * w1v, 0.f);
    }
    __syncthreads();

    // ---- Main: 2 walkers per 16-lane group ----
    const int gt    = blockIdx.x * BLOCK + tid;
    const int group = gt >> 4;
    const int sub   = gt & (TPW - 1);

    const ulonglong2* zA4 = reinterpret_cast<const ulonglong2*>(x + (2 * group)     * NIN);
    const ulonglong2* zB4 = reinterpret_cast<const ulonglong2*>(x + (2 * group + 1) * NIN);
    unsigned long long zA[12], zB[12];
    #pragma unroll
    for (int c = 0; c < 6; c++) {
        ulonglong2 va = zA4[c]; zA[2*c] = va.x; zA[2*c+1] = va.y;
        ulonglong2 vb = zB4[c]; zB[2*c] = vb.x; zB[2*c+1] = vb.y;
    }

    unsigned long long gA[12], gB[12];
    #pragma unroll
    for (int q = 0; q < 12; q++) { gA[q] = 0ull; gB[q] = 0ull; }
    float lapA = 0.f, lapB = 0.f;

    #pragma unroll 4
    for (int jj = 0; jj < HID / TPW; jj++) {
        const int j = (jj << 4) + sub;
        const float* wc = &sW1t[j * STR];

        unsigned long long w_pk[12];
        #pragma unroll
        for (int c = 0; c < 6; c++) {
            const float4 v = *reinterpret_cast<const float4*>(wc + 4 * c);  // LDS.128
            w_pk[2*c]     = pk2(v.x, v.y);
            w_pk[2*c + 1] = pk2(v.z, v.w);
        }
        const float4 p = sP[j];                // (b1, W2, -2*S*W2, 0) broadcast-free LDS.128

        // dots for both walkers (packed over i): 12 FFMA2 each
        unsigned long long aA0 = pk2(p.x, 0.f), aA1 = 0ull, aA2 = 0ull, aA3 = 0ull;
        unsigned long long aB0 = pk2(p.x, 0.f), aB1 = 0ull, aB2 = 0ull, aB3 = 0ull;
        #pragma unroll
        for (int q = 0; q < 12; q += 4) {
            aA0 = ffma2(zA[q],     w_pk[q],     aA0);
            aA1 = ffma2(zA[q + 1], w_pk[q + 1], aA1);
            aA2 = ffma2(zA[q + 2], w_pk[q + 2], aA2);
            aA3 = ffma2(zA[q + 3], w_pk[q + 3], aA3);
            aB0 = ffma2(zB[q],     w_pk[q],     aB0);
            aB1 = ffma2(zB[q + 1], w_pk[q + 1], aB1);
            aB2 = ffma2(zB[q + 2], w_pk[q + 2], aB2);
            aB3 = ffma2(zB[q + 3], w_pk[q + 3], aB3);
        }
        float loA, hiA, loB, hiB;
        upk2(fadd2(fadd2(aA0, aA1), fadd2(aA2, aA3)), loA, hiA);
        upk2(fadd2(fadd2(aB0, aB1), fadd2(aB2, aB3)), loB, hiB);

        // hardware tanh; om = 1-h^2 (non-saturated regime)
        const float hA  = tanh_hw(loA + hiA);
        const float hB  = tanh_hw(loB + hiB);
        const float omA = fmaf(-hA, hA, 1.f);
        const float omB = fmaf(-hB, hB, 1.f);
        const float uA  = omA * p.y;
        const float uB  = omB * p.y;
        lapA = fmaf(omA * hA, p.z, lapA);
        lapB = fmaf(omB * hB, p.z, lapB);

        const unsigned long long dA = pk2(uA, uA);
        const unsigned long long dB = pk2(uB, uB);
        #pragma unroll
        for (int q = 0; q < 12; q++) {
            gA[q] = ffma2(w_pk[q], dA, gA[q]);
            gB[q] = ffma2(w_pk[q], dB, gB[q]);
        }
    }

    // Butterfly reduction across the 16 lanes of this group
    #pragma unroll
    for (int ofs = 1; ofs < TPW; ofs <<= 1) {
        #pragma unroll
        for (int q = 0; q < 12; q++) {
            gA[q] = fadd2(gA[q], __shfl_xor_sync(0xffffffffu, gA[q], ofs));
            gB[q] = fadd2(gB[q], __shfl_xor_sync(0xffffffffu, gB[q], ofs));
        }
        lapA += __shfl_xor_sync(0xffffffffu, lapA, ofs);
        lapB += __shfl_xor_sync(0xffffffffu, lapB, ofs);
    }

    if (sub == 0) {
        unsigned long long gsA = 0ull, gsB = 0ull;
        #pragma unroll
        for (int q = 0; q < 12; q++) {
            gsA = ffma2(gA[q], gA[q], gsA);
            gsB = ffma2(gB[q], gB[q], gsB);
        }
        float la, ha, lb, hb;
        upk2(gsA, la, ha);
        upk2(gsB, lb, hb);
        float2 res;
        res.x = -0.5f * (lapA + (la + ha));
        res.y = -0.5f * (lapB + (lb + hb));
        *reinterpret_cast<float2*>(out + 2 * group) = res;   // 8B-aligned
    }
}

extern "C" void kernel_launch(void* const* d_in, const int* in_sizes, int n_in,
                              void* d_out, int out_size)
{
    // metadata order: x [4096*8*3], W1 [24*256], b1 [256], W2 [256], b2 [1]
    const float* x  = (const float*)d_in[0];
    const float* W1 = (const float*)d_in[1];
    const float* b1 = (const float*)d_in[2];
    const float* W2 = (const float*)d_in[3];
    float* out = (float*)d_out;

    // Single graph node: 256 blocks x 128 threads; 16 walkers per block.
    kin_kernel<<<NWALK / 16, BLOCK>>>(x, W1, b1, W2, out);
}